// round 14
// baseline (speedup 1.0000x reference)
#include <cuda_runtime.h>
#include <stdint.h>

// ---------------------------------------------------------------------------
// KMaxPool: per row of 4096 fp32, top-8 values in original index order.
// TWO warps per row (one half-row each, 4 iters of the proven R10 body),
// then an exact 2x8 sorted-list merge via smem + bitonic max-trick.
//   - warp top-8 DISTRIBUTED in lanes 0..7 (val desc, idx asc on ties)
//   - quad gate: one ballot per 4 elements; hits -> exact per-element inserts
//   - halving the per-warp iteration count halves the serial latency chain
//     (R10/R12/R13 plateau at ~48us with nothing saturated = chain-depth bound)
//   - merge: keys = (monotone val bits)<<32 | ~idx; lists are key-sorted, so
//     c[i]=max(a[i],b[7-i]) + 3-stage bitonic clean gives exact top-8
// ---------------------------------------------------------------------------

#define FULLMASK 0xffffffffu

static __device__ __forceinline__ unsigned long long fkey(float v, uint32_t idx) {
    uint32_t b = __float_as_uint(v);
    uint32_t u = (b & 0x80000000u) ? ~b : (b | 0x80000000u);  // monotone in v
    return ((unsigned long long)u << 32) | (uint32_t)(~idx);
}

static __device__ __forceinline__ float kval(unsigned long long k) {
    uint32_t u = (uint32_t)(k >> 32);
    uint32_t b = (u & 0x80000000u) ? (u ^ 0x80000000u) : ~u;
    return __uint_as_float(b);
}

// Exact per-element processing (uniform ballot loop + distributed insert).
static __device__ __forceinline__ void proc(float v, uint32_t ubase,
                                            float& val, uint32_t& idx,
                                            float& vmin, bool lane0) {
    unsigned m = __ballot_sync(FULLMASK, v > vmin);
    while (m) {
        const int L = __ffs(m) - 1;
        m &= m - 1;
        const float    bv = __shfl_sync(FULLMASK, v, L);
        const uint32_t bi = ubase + ((uint32_t)L << 2);

        const float    pv = __shfl_up_sync(FULLMASK, val, 1);
        const uint32_t pi = __shfl_up_sync(FULLMASK, idx, 1);
        const bool keep = (val >= bv);            // incumbent wins ties
        const bool pk   = lane0 || (pv >= bv);    // lane0: conceptual prev=+inf
        val = keep ? val : (pk ? bv : pv);
        idx = keep ? idx : (pk ? bi : pi);

        vmin = __shfl_sync(FULLMASK, val, 7);
        if (!m) break;
        m &= __ballot_sync(FULLMASK, v > vmin);   // prune with tighter vmin
    }
}

// Quad: one ballot per 4 elements; exact path only on a hit.
static __device__ __forceinline__ void quad(uint4 q, uint32_t ubase,
                                            float& val, uint32_t& idx,
                                            float& vmin, bool lane0) {
    const float vx = __uint_as_float(q.x);
    const float vy = __uint_as_float(q.y);
    const float vz = __uint_as_float(q.z);
    const float vw = __uint_as_float(q.w);
    const float qm = fmaxf(fmaxf(vx, vy), fmaxf(vz, vw));
    if (__ballot_sync(FULLMASK, qm > vmin)) {
        proc(vx, ubase + 0, val, idx, vmin, lane0);
        proc(vy, ubase + 1, val, idx, vmin, lane0);
        proc(vz, ubase + 2, val, idx, vmin, lane0);
        proc(vw, ubase + 3, val, idx, vmin, lane0);
    }
}

__global__ void __launch_bounds__(128) kmax8_kernel(const float* __restrict__ x,
                                                    float* __restrict__ out,
                                                    int nrows) {
    __shared__ unsigned long long keys[4][8];

    const int warp = (int)(threadIdx.x >> 5);    // 0..3
    const int lane = threadIdx.x & 31;
    const int r    = blockIdx.x * 2 + (warp >> 1);
    const int half = warp & 1;                   // which half-row this warp scans
    const bool active = (r < nrows);
    const bool lane0  = (lane == 0);

    float    val  = __int_as_float(0xff800000);  // -inf (lanes 0..7 = top-8)
    uint32_t idx  = 0;
    float    vmin = __int_as_float(0xff800000);

    if (active) {
        const uint4* base = reinterpret_cast<const uint4*>(x) +
                            (size_t)r * 1024 + half * 512;
        const uint32_t ebase = (uint32_t)half * 2048u;

        // 4 batches x (4 float4 loads = 16 elements) per lane = 2048 elems.
#pragma unroll 1
        for (int it = 0; it < 4; ++it) {
            const uint4* p = base + it * 128 + lane;
            uint4 a = p[0];
            uint4 b = p[32];
            uint4 c = p[64];
            uint4 d = p[96];

            const uint32_t u0 = ebase + (uint32_t)(it * 512);
            quad(a, u0 + 0,   val, idx, vmin, lane0);
            quad(b, u0 + 128, val, idx, vmin, lane0);
            quad(c, u0 + 256, val, idx, vmin, lane0);
            quad(d, u0 + 384, val, idx, vmin, lane0);
        }
    }

    // Publish this warp's sorted-desc 8-list as u64 keys.
    if (lane < 8) keys[warp][lane] = active ? fkey(val, idx) : 0ull;
    __syncthreads();

    // Even warps merge their pair's two sorted lists exactly.
    if (half == 0 && active) {
        unsigned long long k = 0ull;
        if (lane < 8) {
            unsigned long long a = keys[warp][lane];
            unsigned long long b = keys[warp + 1][7 - lane];
            k = (a > b) ? a : b;                 // top-8 of union, bitonic
        }
        // 3-stage bitonic clean (descending) over lanes 0..7.
#pragma unroll
        for (int j = 4; j >= 1; j >>= 1) {
            unsigned long long o = __shfl_xor_sync(FULLMASK, k, j);
            const bool up = ((lane & j) == 0);
            k = up ? ((k > o) ? k : o) : ((k < o) ? k : o);
        }
        // Decode and scatter by ascending original index.
        const float    v  = kval(k);
        const uint32_t id = ~(uint32_t)k;
        int rank = 0;
#pragma unroll
        for (int dd = 1; dd < 8; ++dd) {
            uint32_t oi = __shfl_sync(FULLMASK, id, (lane + dd) & 7);
            rank += (oi < id) ? 1 : 0;
        }
        if (lane < 8) out[(size_t)r * 8 + rank] = v;
    }
}

extern "C" void kernel_launch(void* const* d_in, const int* in_sizes, int n_in,
                              void* d_out, int out_size) {
    const float* x = (const float*)d_in[0];
    float* out = (float*)d_out;
    int nrows = in_sizes[0] / 4096;
    // 2 warps per row, 4 warps (2 rows) per 128-thread block
    int blocks = (nrows + 1) / 2;
    kmax8_kernel<<<blocks, 128>>>(x, out, nrows);
}

// round 15
// speedup vs baseline: 1.3799x; 1.3799x over previous
#include <cuda_runtime.h>
#include <stdint.h>

// ---------------------------------------------------------------------------
// KMaxPool: per row of 4096 fp32, top-8 values in original index order.
// One warp per row, single pass. Structure identical to R10 (best: 47.6us):
//   - warp top-8 DISTRIBUTED in lanes 0..7 (val desc), vmin = lane7 val
//   - quad gate: one ballot per 4 elements; hits -> exact per-element inserts
//   - epilogue: rank lanes 0..7 by original index, scatter-store 8 floats
// ONE change: phase-split insert path.
//   it==0 (warm-up flood): PRUNED pop loop (re-ballot + per-pop vmin refresh)
//   it>=1 (sparse hits):   LEAN pop loop (no re-ballot; stale pops are
//     provable no-ops since bv <= val[7] => keep on every lane; vmin
//     refreshed once after the loop). Cuts per-insert serial latency ~2.5x
//     and ~6 slots/insert in steady state, where inserts are ~70% of the
//     non-load issue budget (R14 post-mortem).
// ---------------------------------------------------------------------------

#define FULLMASK 0xffffffffu

// Exact per-element processing. PRUNE=true: re-ballot after each pop (cheap
// when many lanes qualify). PRUNE=false: pop the initial mask only.
template <bool PRUNE>
static __device__ __forceinline__ void proc(float v, uint32_t ubase,
                                            float& val, uint32_t& idx,
                                            float& vmin, bool lane0) {
    unsigned m = __ballot_sync(FULLMASK, v > vmin);
    if (!m) return;
    do {
        const int L = __ffs(m) - 1;
        m &= m - 1;
        const float    bv = __shfl_sync(FULLMASK, v, L);
        const uint32_t bi = ubase + ((uint32_t)L << 2);

        const float    pv = __shfl_up_sync(FULLMASK, val, 1);
        const uint32_t pi = __shfl_up_sync(FULLMASK, idx, 1);
        const bool keep = (val >= bv);            // incumbent wins ties
        const bool pk   = lane0 || (pv >= bv);    // lane0: conceptual prev=+inf
        val = keep ? val : (pk ? bv : pv);
        idx = keep ? idx : (pk ? bi : pi);

        if (PRUNE) {
            vmin = __shfl_sync(FULLMASK, val, 7);
            if (!m) break;
            m &= __ballot_sync(FULLMASK, v > vmin);
        }
    } while (m);
    if (!PRUNE) vmin = __shfl_sync(FULLMASK, val, 7);
}

// Quad: one ballot per 4 elements; exact path only on a hit.
template <bool PRUNE>
static __device__ __forceinline__ void quad(uint4 q, uint32_t ubase,
                                            float& val, uint32_t& idx,
                                            float& vmin, bool lane0) {
    const float vx = __uint_as_float(q.x);
    const float vy = __uint_as_float(q.y);
    const float vz = __uint_as_float(q.z);
    const float vw = __uint_as_float(q.w);
    const float qm = fmaxf(fmaxf(vx, vy), fmaxf(vz, vw));
    if (__ballot_sync(FULLMASK, qm > vmin)) {
        proc<PRUNE>(vx, ubase + 0, val, idx, vmin, lane0);
        proc<PRUNE>(vy, ubase + 1, val, idx, vmin, lane0);
        proc<PRUNE>(vz, ubase + 2, val, idx, vmin, lane0);
        proc<PRUNE>(vw, ubase + 3, val, idx, vmin, lane0);
    }
}

__global__ void __launch_bounds__(256) kmax8_kernel(const float* __restrict__ x,
                                                    float* __restrict__ out,
                                                    int nrows) {
    const int gw   = (int)((blockIdx.x * blockDim.x + threadIdx.x) >> 5);
    const int lane = threadIdx.x & 31;
    if (gw >= nrows) return;

    const uint4* row = reinterpret_cast<const uint4*>(x) + (size_t)gw * 1024;

    float    val  = __int_as_float(0xff800000);  // -inf (lanes 0..7 = top-8)
    uint32_t idx  = 0;
    float    vmin = __int_as_float(0xff800000);
    const bool lane0 = (lane == 0);

    // it = 0: warm-up with pruned inserts (ballots can be dense).
    {
        const int p0 = lane;
        uint4 a = row[p0];
        uint4 b = row[p0 + 32];
        uint4 c = row[p0 + 64];
        uint4 d = row[p0 + 96];
        quad<true>(a, 0u,   val, idx, vmin, lane0);
        quad<true>(b, 128u, val, idx, vmin, lane0);
        quad<true>(c, 256u, val, idx, vmin, lane0);
        quad<true>(d, 384u, val, idx, vmin, lane0);
    }

    // it = 1..7: lean inserts (ballots sparse; stale pops are no-ops).
#pragma unroll 1
    for (int it = 1; it < 8; ++it) {
        const int p0 = it * 128 + lane;
        uint4 a = row[p0];
        uint4 b = row[p0 + 32];
        uint4 c = row[p0 + 64];
        uint4 d = row[p0 + 96];

        const uint32_t u0 = (uint32_t)(it * 512);
        quad<false>(a, u0 + 0,   val, idx, vmin, lane0);
        quad<false>(b, u0 + 128, val, idx, vmin, lane0);
        quad<false>(c, u0 + 256, val, idx, vmin, lane0);
        quad<false>(d, u0 + 384, val, idx, vmin, lane0);
    }

    // Epilogue: lanes 0..7 hold the top-8 (val desc, unique idx).
    // rank = number of held indices smaller than mine -> output position.
    int rank = 0;
#pragma unroll
    for (int dd = 1; dd < 8; ++dd) {
        uint32_t oi = __shfl_sync(FULLMASK, idx, (lane + dd) & 7);
        rank += (oi < idx) ? 1 : 0;
    }
    if (lane < 8) out[(size_t)gw * 8 + rank] = val;
}

extern "C" void kernel_launch(void* const* d_in, const int* in_sizes, int n_in,
                              void* d_out, int out_size) {
    const float* x = (const float*)d_in[0];
    float* out = (float*)d_out;
    int nrows = in_sizes[0] / 4096;
    const int threads = 256;
    const int warps_per_block = threads / 32;
    int blocks = (nrows + warps_per_block - 1) / warps_per_block;
    kmax8_kernel<<<blocks, threads>>>(x, out, nrows);
}